// round 17
// baseline (speedup 1.0000x reference)
#include <cuda_runtime.h>
#include <math.h>
#include <stdint.h>

typedef unsigned long long ull;

// ---------------- problem constants ----------------
constexpr int CH   = 120;
constexpr int NWIN = 1024;          // total windows (4 * 4 * 8 * 8)
constexpr int NTOK = NWIN * 128;    // 131072
constexpr float SCALE_F = 0.22360679774997896f;  // 20^-0.5

// ---------------- scratch ----------------
__device__ float g_xw   [(size_t)NTOK * CH];    // LN1'd (tf32-rounded)
__device__ float g_xwm  [(size_t)NTOK * CH];    // g_xw + pos (tf32-rounded)
__device__ float g_qkv_s[(size_t)NTOK * 360];   // layout [win][360][128]
__device__ float g_qkv_m[(size_t)NTOK * 360];   // layout [win][360][128]
__device__ float g_xout [(size_t)NTOK * 240];   // [win][240][128] (tf32-rounded)
__device__ float g_xres [(size_t)NTOK * CH];    // x + attn branch (exact)
__device__ float g_z    [(size_t)NTOK * CH];    // LN2 out (tf32-rounded)
__device__ float g_h    [(size_t)NTOK * 480];   // fc11|fc12 pre-activations
__device__ float g_act  [(size_t)NTOK * 240];   // gelu gate (tf32-rounded)
__device__ float g_wts  [259200];               // tf32-rounded weights

// weight buffer offsets
constexpr int W_QS  = 0;        // qkv_self_w 43200
constexpr int W_QM  = 43200;    // qkv_mut_w  43200
constexpr int W_PR  = 86400;    // proj_w     28800
constexpr int W_F11 = 115200;   // fc11_w     57600
constexpr int W_F12 = 172800;   // fc12_w     57600
constexpr int W_F2  = 230400;   // fc2_w      28800

// ---------------- helpers ----------------
__device__ __forceinline__ float f2tf32(float f) {
    uint32_t r; asm("cvt.rna.tf32.f32 %0, %1;" : "=r"(r) : "f"(f));
    return __uint_as_float(r);
}
__device__ __forceinline__ void mma_tf32(float* d, const uint32_t* a,
                                         const uint32_t* b) {
    asm("mma.sync.aligned.m16n8k8.row.col.f32.tf32.tf32.f32 "
        "{%0,%1,%2,%3},{%4,%5,%6,%7},{%8,%9},{%0,%1,%2,%3};"
        : "+f"(d[0]), "+f"(d[1]), "+f"(d[2]), "+f"(d[3])
        : "r"(a[0]), "r"(a[1]), "r"(a[2]), "r"(a[3]), "r"(b[0]), "r"(b[1]));
}
__device__ __forceinline__ void cp16(float* smem_dst, const float* gsrc,
                                     bool pred) {
    uint32_t sa = (uint32_t)__cvta_generic_to_shared(smem_dst);
    int sz = pred ? 16 : 0;
    asm volatile("cp.async.ca.shared.global [%0], [%1], 16, %2;"
                 :: "r"(sa), "l"(gsrc), "r"(sz));
}
#define CP_COMMIT() asm volatile("cp.async.commit_group;")

__device__ __forceinline__ float gelu_exact(float v) {
    return 0.5f * v * (1.0f + erff(v * 0.70710678118654752f));
}
// pair-swizzle within each 8-group: {0,4,1,5,2,6,3,7} so (i, i+4) are adjacent
__device__ __forceinline__ int pswz(int d) {
    return (d & ~7) + ((d & 3) << 1) + ((d & 7) >> 2);
}

// token (wi,t) -> rolled source/dest offset in (B,D,H,W,C) layout
__device__ __forceinline__ size_t roll_offset(int wi, int t) {
    int wB = wi & 7, hB = (wi >> 3) & 7, dB = (wi >> 6) & 3, bb = wi >> 8;
    int dt = t >> 6, ht = (t >> 3) & 7, wt = t & 7;
    int ds = (dB * 2 + dt + 1) & 7;
    int hs = (hB * 8 + ht + 4) & 63;
    int ws = (wB * 8 + wt + 4) & 63;
    return (size_t)((((bb * 8 + ds) * 64 + hs) * 64 + ws)) * CH;
}

// ---------------- K0: round all weights to tf32 once per launch ----------
__global__ void k_wcvt(const float* __restrict__ qs, const float* __restrict__ qm,
                       const float* __restrict__ pr, const float* __restrict__ f11,
                       const float* __restrict__ f12, const float* __restrict__ f2) {
    int i4 = blockIdx.x * blockDim.x + threadIdx.x;
    if (i4 >= 64800) return;
    int i = i4 * 4;
    const float* src;
    int off;
    if (i < 43200)       { src = qs;  off = i; }
    else if (i < 86400)  { src = qm;  off = i - 43200; }
    else if (i < 115200) { src = pr;  off = i - 86400; }
    else if (i < 172800) { src = f11; off = i - 115200; }
    else if (i < 230400) { src = f12; off = i - 172800; }
    else                 { src = f2;  off = i - 230400; }
    float4 v = *(const float4*)(src + off);
    v.x = f2tf32(v.x); v.y = f2tf32(v.y);
    v.z = f2tf32(v.z); v.w = f2tf32(v.w);
    *(float4*)(g_wts + i) = v;
}

// ---------------- K1: LN1 + roll + window partition (+pos variant) -------
__global__ void k_ln1(const float* __restrict__ x, const float* __restrict__ g,
                      const float* __restrict__ b, const float* __restrict__ pos) {
    int warp = (blockIdx.x * blockDim.x + threadIdx.x) >> 5;
    int lane = threadIdx.x & 31;
    if (warp >= NTOK) return;
    int wi = warp >> 7, t = warp & 127;
    const float* src = x + roll_offset(wi, t);
    float v0 = 0, v1 = 0, v2 = 0, v3 = 0, s = 0, sq = 0;
    if (lane < 30) {
        float4 f = *(const float4*)(src + lane * 4);
        v0 = f.x; v1 = f.y; v2 = f.z; v3 = f.w;
        s  = v0 + v1 + v2 + v3;
        sq = v0 * v0 + v1 * v1 + v2 * v2 + v3 * v3;
    }
#pragma unroll
    for (int o = 16; o; o >>= 1) {
        s  += __shfl_xor_sync(0xffffffffu, s, o);
        sq += __shfl_xor_sync(0xffffffffu, sq, o);
    }
    float mean = s * (1.0f / 120.0f);
    float var  = sq * (1.0f / 120.0f) - mean * mean;
    float r = rsqrtf(var + 1e-5f);
    if (lane < 30) {
        int c = lane * 4;
        float y0 = (v0 - mean) * r * g[c]     + b[c];
        float y1 = (v1 - mean) * r * g[c + 1] + b[c + 1];
        float y2 = (v2 - mean) * r * g[c + 2] + b[c + 2];
        float y3 = (v3 - mean) * r * g[c + 3] + b[c + 3];
        float* dst = g_xw + (size_t)warp * CH + c;
        dst[0] = f2tf32(y0); dst[1] = f2tf32(y1);
        dst[2] = f2tf32(y2); dst[3] = f2tf32(y3);
        float4 pv = *(const float4*)(pos + (size_t)(t & 63) * CH + c);
        float* dm = g_xwm + (size_t)warp * CH + c;
        dm[0] = f2tf32(y0 + pv.x); dm[1] = f2tf32(y1 + pv.y);
        dm[2] = f2tf32(y2 + pv.z); dm[3] = f2tf32(y3 + pv.w);
    }
}

// ---------------- LN2 (plain layout, tf32-rounded out) ----------------
__global__ void k_ln2(const float* __restrict__ g, const float* __restrict__ b) {
    int warp = (blockIdx.x * blockDim.x + threadIdx.x) >> 5;
    int lane = threadIdx.x & 31;
    if (warp >= NTOK) return;
    const float* src = g_xres + (size_t)warp * CH;
    float v0 = 0, v1 = 0, v2 = 0, v3 = 0, s = 0, sq = 0;
    if (lane < 30) {
        float4 f = *(const float4*)(src + lane * 4);
        v0 = f.x; v1 = f.y; v2 = f.z; v3 = f.w;
        s  = v0 + v1 + v2 + v3;
        sq = v0 * v0 + v1 * v1 + v2 * v2 + v3 * v3;
    }
#pragma unroll
    for (int o = 16; o; o >>= 1) {
        s  += __shfl_xor_sync(0xffffffffu, s, o);
        sq += __shfl_xor_sync(0xffffffffu, sq, o);
    }
    float mean = s * (1.0f / 120.0f);
    float var  = sq * (1.0f / 120.0f) - mean * mean;
    float r = rsqrtf(var + 1e-5f);
    if (lane < 30) {
        int c = lane * 4;
        float* dst = g_z + (size_t)warp * CH + c;
        dst[0] = f2tf32((v0 - mean) * r * g[c]     + b[c]);
        dst[1] = f2tf32((v1 - mean) * r * g[c + 1] + b[c + 1]);
        dst[2] = f2tf32((v2 - mean) * r * g[c + 2] + b[c + 2]);
        dst[3] = f2tf32((v3 - mean) * r * g[c + 3] + b[c + 3]);
    }
}

// ---------------- gated-gelu elementwise (tf32-rounded out) ----------------
__global__ void k_act() {
    int idx = blockIdx.x * blockDim.x + threadIdx.x;
    if (idx >= NTOK * 60) return;
    int m = idx / 60, c4 = (idx % 60) * 4;
    const float* hp = g_h + (size_t)m * 480 + c4;
    float4 h1 = *(const float4*)hp;
    float4 h2 = *(const float4*)(hp + 240);
    float4 o;
    o.x = f2tf32(gelu_exact(h1.x) * h2.x);
    o.y = f2tf32(gelu_exact(h1.y) * h2.y);
    o.z = f2tf32(gelu_exact(h1.z) * h2.z);
    o.w = f2tf32(gelu_exact(h1.w) * h2.w);
    *(float4*)(g_act + (size_t)m * 240 + c4) = o;
}

// ---------------- tf32 tensor-core GEMM, cp.async 3-stage pipeline -------
template <int KD, int MODE, int OUTT, int EPI>
__global__ void __launch_bounds__(256) k_gemm(
    const float* __restrict__ A, const float* __restrict__ B1,
    const float* __restrict__ B2, const float* __restrict__ bias,
    const float* __restrict__ bias2, const float* __restrict__ extra,
    float* __restrict__ out, int Ntot) {
    constexpr int S = KD / 8;
    __shared__ __align__(16) float sm[3 * 3072];
    int tid = threadIdx.x;
    int m0 = blockIdx.x * 128;
    int n0 = blockIdx.y * 128;
    int win = m0 >> 7;
    int warp = tid >> 5, lane = tid & 31;
    int g = lane >> 2, th = lane & 3;
    int wm = (warp & 1) * 64;
    int wn = (warp >> 1) * 32;
    int lr = tid >> 1;          // load row 0..127
    int lc = (tid & 1) * 4;     // load col offset (0 or 4)
    int kk = tid >> 5;          // MODE2: k row 0..7
    int mc = (tid & 31) * 4;    // MODE2: m col

    float d[4][4][4];
#pragma unroll
    for (int i = 0; i < 4; i++)
#pragma unroll
        for (int j = 0; j < 4; j++)
#pragma unroll
            for (int r = 0; r < 4; r++) d[i][j][r] = 0.0f;

    int am = m0 + lr;
    int bn = n0 + lr;
    bool bvalid = bn < Ntot;
    const float* bsrc;
    if (EPI == 3) {
        bsrc = (bn < 240) ? (B1 + (size_t)bn * KD)
                          : (B2 + (size_t)(bn - 240) * KD);
    } else {
        bsrc = B1 + (size_t)(bvalid ? bn : 0) * KD;
    }

    auto issue = [&](int s, int off) {
        float* base = sm + off;
        int k0 = s * 8;
        if (MODE == 2) {
            cp16(base + kk * 132 + mc,
                 A + ((size_t)win * 240 + k0 + kk) * 128 + mc, true);
        } else {
            cp16(base + lr * 12 + lc, A + (size_t)am * KD + k0 + lc, true);
        }
        cp16(base + 1536 + lr * 12 + lc, bsrc + k0 + lc, bvalid);
        CP_COMMIT();
    };

    issue(0, 0);
    issue(1, 3072);

    int c_off = 0, p_off = 2 * 3072;
#pragma unroll 1
    for (int s = 0; s < S; s++) {
        if (s + 1 < S) asm volatile("cp.async.wait_group 1;");
        else           asm volatile("cp.async.wait_group 0;");
        __syncthreads();

        const float* As = sm + c_off;
        const float* Bs = As + 1536;
        uint32_t a[4][4], b[4][2];
#pragma unroll
        for (int i = 0; i < 4; i++) {
            int m1 = wm + i * 16 + g;
            if (MODE == 2) {
                a[i][0] = __float_as_uint(As[th * 132 + m1]);
                a[i][1] = __float_as_uint(As[th * 132 + m1 + 8]);
                a[i][2] = __float_as_uint(As[(th + 4) * 132 + m1]);
                a[i][3] = __float_as_uint(As[(th + 4) * 132 + m1 + 8]);
            } else {
                const float* base = As + m1 * 12;
                a[i][0] = __float_as_uint(base[th]);
                a[i][1] = __float_as_uint(base[96 + th]);
                a[i][2] = __float_as_uint(base[th + 4]);
                a[i][3] = __float_as_uint(base[96 + th + 4]);
            }
        }
#pragma unroll
        for (int j = 0; j < 4; j++) {
            const float* base = Bs + (wn + j * 8 + g) * 12;
            b[j][0] = __float_as_uint(base[th]);
            b[j][1] = __float_as_uint(base[th + 4]);
        }
#pragma unroll
        for (int i = 0; i < 4; i++)
#pragma unroll
            for (int j = 0; j < 4; j++) mma_tf32(d[i][j], a[i], b[j]);

        if (s + 2 < S) issue(s + 2, p_off);
        c_off = (c_off == 6144) ? 0 : c_off + 3072;
        p_off = (p_off == 6144) ? 0 : p_off + 3072;
    }

    if (OUTT == 1) {
        __syncthreads();
        int nrow = tid >> 4;
        int mcol = (tid & 15) * 8;
#pragma unroll 1
        for (int c = 0; c < 8; c++) {
            if ((wn >> 5) == (c >> 1)) {
                int jbase = (c & 1) * 2;
#pragma unroll
                for (int jj = 0; jj < 2; jj++) {
                    int j = jbase + jj;
#pragma unroll
                    for (int i = 0; i < 4; i++)
#pragma unroll
                        for (int r = 0; r < 4; r++) {
                            int nl = j * 8 + 2 * th + (r & 1) - (c & 1) * 16;
                            int m  = wm + i * 16 + g + (r >> 1) * 8;
                            sm[nl * 128 + m] = d[i][j][r];
                        }
                }
            }
            __syncthreads();
            int n = n0 + c * 16 + nrow;
            if (n < Ntot) {
                float bz = bias[n];
                float4 x1 = *(float4*)&sm[nrow * 128 + mcol];
                float4 x2 = *(float4*)&sm[nrow * 128 + mcol + 4];
                x1.x += bz; x1.y += bz; x1.z += bz; x1.w += bz;
                x2.x += bz; x2.y += bz; x2.z += bz; x2.w += bz;
                float* op = out + ((size_t)win * 360 + n) * 128 + mcol;
                *(float4*)op = x1;
                *(float4*)(op + 4) = x2;
            }
            __syncthreads();
        }
        return;
    }

#pragma unroll
    for (int i = 0; i < 4; i++)
#pragma unroll
        for (int rh = 0; rh < 2; rh++) {
            int m = m0 + wm + i * 16 + g + rh * 8;
            size_t drow;
            if (EPI == 2) {
                drow = roll_offset(m >> 7, m & 127);
            } else {
                drow = (size_t)m * Ntot;
            }
#pragma unroll
            for (int j = 0; j < 4; j++) {
                int n = n0 + wn + j * 8 + 2 * th;
                if (n >= Ntot) continue;
                float2 v = make_float2(d[i][j][rh * 2], d[i][j][rh * 2 + 1]);
                if (EPI == 2) {
                    const float* e = extra + drow + n;
                    v.x += bias[n] + e[0];
                    v.y += bias[n + 1] + e[1];
                } else if (EPI == 3) {
                    const float* bp = (n < 240) ? (bias + n) : (bias2 + n - 240);
                    v.x += bp[0];
                    v.y += bp[1];
                } else {
                    const float* e = extra + (size_t)m * 120 + n;
                    v.x += bias[n] + e[0];
                    v.y += bias[n + 1] + e[1];
                }
                *(float2*)(out + drow + n) = v;
            }
        }
}

// ---------------- K4: tensor-core attention, block = (window, head) -------
// 256 threads, warp w owns output rows [16w, 16w+16).
// S = Q K^T (m16n8k8 tf32, d padded to 24), fragment softmax, P V via
// register-shuffle fragment transpose. K smem [t][24] pair-swizzled dims;
// V smem transposed [24][132] pair-swizzled tokens.
__global__ void __launch_bounds__(256) k_attn(const float* __restrict__ rpb) {
    __shared__ __align__(16) float sk [128 * 24];
    __shared__ __align__(16) float svT[24 * 132];
    __shared__ __align__(16) float srpb[676];
    __shared__ __align__(16) int   sg[128];

    int wi = blockIdx.x, h = blockIdx.y;
    int tid = threadIdx.x;
    int w = tid >> 5, lane = tid & 31;
    int g = lane >> 2, th = lane & 3;

    for (int i = tid; i < 675; i += 256) srpb[i] = rpb[i * 6 + h];
    if (tid < 128) {
        int t = tid;
        int dt = t >> 6, ht = (t >> 3) & 7, wt = t & 7;
        int dB = (wi >> 6) & 3, hB = (wi >> 3) & 7, wB = wi & 7;
        int dd = dB * 2 + dt, hh = hB * 8 + ht, ww = wB * 8 + wt;
        int gd = (dd < 6) ? 0 : ((dd < 7) ? 1 : 2);
        int gh = (hh < 56) ? 0 : ((hh < 60) ? 1 : 2);
        int gw = (ww < 56) ? 0 : ((ww < 60) ? 1 : 2);
        int grp = gd * 9 + gh * 3 + gw;
        int gd0 = (dB * 2 < 6) ? 0 : 1;
        int grp0 = gd0 * 9 + gh * 3 + gw;
        int ccode = dt * 225 + ht * 15 + wt;
        sg[t] = ccode | (grp << 10) | (grp0 << 16);
    }

    const float* Qs = g_qkv_s + (size_t)wi * 360 * 128;
    const float* Qm = g_qkv_m + (size_t)wi * 360 * 128;

    // fill K/V (self), zero pads
    for (int i = tid; i < 2560; i += 256) {
        int dd = i >> 7, t = i & 127;
        sk [t * 24 + pswz(dd)]   = f2tf32(Qs[(120 + h * 20 + dd) * 128 + t]);
        svT[dd * 132 + pswz(t)]  = f2tf32(Qs[(240 + h * 20 + dd) * 128 + t]);
    }
    for (int i = tid; i < 512; i += 256) {
        int t = i >> 2, dd = 20 + (i & 3);
        sk[t * 24 + pswz(dd)] = 0.f;
    }
    for (int i = tid; i < 512; i += 256) {
        int dd = 20 + (i >> 7), t = i & 127;
        svT[dd * 132 + t] = 0.f;
    }
    __syncthreads();

    int r0 = w * 16;
    int sgrA = sg[r0 + g], sgrB = sg[r0 + 8 + g];
    int rbA = (sgrA & 1023) + 337, rbB = (sgrB & 1023) + 337;
    int grpA = (sgrA >> 10) & 31, grpB = (sgrB >> 10) & 31;
    int sA = (lane & ~3) | (th >> 1);
    int sB = sA + 2;
    bool hi = th & 1;

    float P[16][4];
    float o[3][4];

    // ================= SELF =================
    {
        uint32_t aq[3][4];
#pragma unroll
        for (int ks = 0; ks < 3; ks++) {
            int k0 = ks * 8 + th, k1 = ks * 8 + th + 4;
            float q0 = (k0 < 20) ? Qs[(h * 20 + k0) * 128 + r0 + g]     * SCALE_F : 0.f;
            float q1 = (k0 < 20) ? Qs[(h * 20 + k0) * 128 + r0 + 8 + g] * SCALE_F : 0.f;
            float q2 = (k1 < 20) ? Qs[(h * 20 + k1) * 128 + r0 + g]     * SCALE_F : 0.f;
            float q3 = (k1 < 20) ? Qs[(h * 20 + k1) * 128 + r0 + 8 + g] * SCALE_F : 0.f;
            aq[ks][0] = __float_as_uint(f2tf32(q0));
            aq[ks][1] = __float_as_uint(f2tf32(q1));
            aq[ks][2] = __float_as_uint(f2tf32(q2));
            aq[ks][3] = __float_as_uint(f2tf32(q3));
        }
        float rsA = 0.f, rsB = 0.f;
#pragma unroll
        for (int nt = 0; nt < 16; nt++) {
            float acc[4] = {0.f, 0.f, 0.f, 0.f};
#pragma unroll
            for (int ks = 0; ks < 3; ks++) {
                float2 bb = *(const float2*)&sk[(nt * 8 + g) * 24 + ks * 8 + 2 * th];
                uint32_t b[2] = {__float_as_uint(bb.x), __float_as_uint(bb.y)};
                mma_tf32(acc, aq[ks], b);
            }
            int2 sgc = *(const int2*)&sg[nt * 8 + 2 * th];
            int cc0 = sgc.x & 1023, cc1 = sgc.y & 1023;
            int gc0 = (sgc.x >> 10) & 31, gc1 = (sgc.y >> 10) & 31;
            float p0 = (gc0 == grpA) ? __expf(acc[0] + srpb[rbA - cc0]) : 0.f;
            float p1 = (gc1 == grpA) ? __expf(acc[1] + srpb[rbA - cc1]) : 0.f;
            float p2 = (gc0 == grpB) ? __expf(acc[2] + srpb[rbB - cc0]) : 0.f;
            float p3 = (gc1 == grpB) ? __expf(acc[3] + srpb[rbB - cc1]) : 0.f;
            rsA += p0 + p1; rsB += p2 + p3;
            P[nt][0] = f2tf32(p0); P[nt][1] = f2tf32(p1);
            P[nt][2] = f2tf32(p2); P[nt][3] = f2tf32(p3);
        }
        rsA += __shfl_xor_sync(0xffffffffu, rsA, 1);
        rsA += __shfl_xor_sync(0xffffffffu, rsA, 2);
        rsB += __shfl_xor_sync(0xffffffffu, rsB, 1);
        rsB += __shfl_xor_sync(0xffffffffu, rsB, 2);
        float invA = 1.0f / rsA, invB = 1.0f / rsB;

#pragma unroll
        for (int n2 = 0; n2 < 3; n2++)
#pragma unroll
            for (int r = 0; r < 4; r++) o[n2][r] = 0.f;
#pragma unroll
        for (int kt = 0; kt < 16; kt++) {
            float x0 = __shfl_sync(0xffffffffu, P[kt][0], sA);
            float x1 = __shfl_sync(0xffffffffu, P[kt][1], sA);
            float y0 = __shfl_sync(0xffffffffu, P[kt][0], sB);
            float y1 = __shfl_sync(0xffffffffu, P[kt][1], sB);
            float z0 = __shfl_sync(0xffffffffu, P[kt][2], sA);
            float z1 = __shfl_sync(0xffffffffu, P[kt][3], sA);
            float u0 = __shfl_sync(0xffffffffu, P[kt][2], sB);
            float u1 = __shfl_sync(0xffffffffu, P[kt][3], sB);
            uint32_t a[4];
            a[0] = __float_as_uint(hi ? x1 : x0);
            a[1] = __float_as_uint(hi ? z1 : z0);
            a[2] = __float_as_uint(hi ? y1 : y0);
            a[3] = __float_as_uint(hi ? u1 : u0);
#pragma unroll
            for (int n2 = 0; n2 < 3; n2++) {
                float2 bb = *(const float2*)&svT[(n2 * 8 + g) * 132 + kt * 8 + 2 * th];
                uint32_t b[2] = {__float_as_uint(bb.x), __float_as_uint(bb.y)};
                mma_tf32(o[n2], a, b);
            }
        }
        float* ob = g_xout + ((size_t)wi * 240 + 120 + h * 20) * 128;
#pragma unroll
        for (int n2 = 0; n2 < 3; n2++) {
            int d0 = n2 * 8 + 2 * th, d1 = d0 + 1;
            if (d0 < 20) {
                ob[d0 * 128 + r0 + g]     = f2tf32(o[n2][0] * invA);
                ob[d0 * 128 + r0 + 8 + g] = f2tf32(o[n2][2] * invB);
            }
            if (d1 < 20) {
                ob[d1 * 128 + r0 + g]     = f2tf32(o[n2][1] * invA);
                ob[d1 * 128 + r0 + 8 + g] = f2tf32(o[n2][3] * invB);
            }
        }
    }

    // ================= MUTUAL =================
    __syncthreads();
    for (int i = tid; i < 2560; i += 256) {
        int dd = i >> 7, t = i & 127;
        sk [t * 24 + pswz(dd)]  = f2tf32(Qm[(120 + h * 20 + dd) * 128 + t]);
        svT[dd * 132 + pswz(t)] = f2tf32(Qm[(240 + h * 20 + dd) * 128 + t]);
    }
    __syncthreads();
    {
        int mb = (w < 4) ? 0 : 64;
        int qx = (w ^ 4) * 16;
        uint32_t aq[3][4];
#pragma unroll
        for (int ks = 0; ks < 3; ks++) {
            int k0 = ks * 8 + th, k1 = ks * 8 + th + 4;
            float q0 = (k0 < 20) ? Qm[(h * 20 + k0) * 128 + qx + g]     * SCALE_F : 0.f;
            float q1 = (k0 < 20) ? Qm[(h * 20 + k0) * 128 + qx + 8 + g] * SCALE_F : 0.f;
            float q2 = (k1 < 20) ? Qm[(h * 20 + k1) * 128 + qx + g]     * SCALE_F : 0.f;
            float q3 = (k1 < 20) ? Qm[(h * 20 + k1) * 128 + qx + 8 + g] * SCALE_F : 0.f;
            aq[ks][0] = __float_as_uint(f2tf32(q0));
            aq[ks][1] = __float_as_uint(f2tf32(q1));
            aq[ks][2] = __float_as_uint(f2tf32(q2));
            aq[ks][3] = __float_as_uint(f2tf32(q3));
        }
        int mgA = (sg[(r0 + g) & 63] >> 16) & 31;
        int mgB = (sg[(r0 + 8 + g) & 63] >> 16) & 31;
        float rsA = 0.f, rsB = 0.f;
#pragma unroll
        for (int nt = 0; nt < 8; nt++) {
            float acc[4] = {0.f, 0.f, 0.f, 0.f};
#pragma unroll
            for (int ks = 0; ks < 3; ks++) {
                float2 bb = *(const float2*)&sk[(mb + nt * 8 + g) * 24 + ks * 8 + 2 * th];
                uint32_t b[2] = {__float_as_uint(bb.x), __float_as_uint(bb.y)};
                mma_tf32(acc, aq[ks], b);
            }
            int2 sgc = *(const int2*)&sg[nt * 8 + 2 * th];
            int gc0 = (sgc.x >> 16) & 31, gc1 = (sgc.y >> 16) & 31;
            float p0 = (gc0 == mgA) ? __expf(acc[0]) : 0.f;
            float p1 = (gc1 == mgA) ? __expf(acc[1]) : 0.f;
            float p2 = (gc0 == mgB) ? __expf(acc[2]) : 0.f;
            float p3 = (gc1 == mgB) ? __expf(acc[3]) : 0.f;
            rsA += p0 + p1; rsB += p2 + p3;
            P[nt][0] = f2tf32(p0); P[nt][1] = f2tf32(p1);
            P[nt][2] = f2tf32(p2); P[nt][3] = f2tf32(p3);
        }
        rsA += __shfl_xor_sync(0xffffffffu, rsA, 1);
        rsA += __shfl_xor_sync(0xffffffffu, rsA, 2);
        rsB += __shfl_xor_sync(0xffffffffu, rsB, 1);
        rsB += __shfl_xor_sync(0xffffffffu, rsB, 2);
        float invA = 1.0f / rsA, invB = 1.0f / rsB;

#pragma unroll
        for (int n2 = 0; n2 < 3; n2++)
#pragma unroll
            for (int r = 0; r < 4; r++) o[n2][r] = 0.f;
#pragma unroll
        for (int kt = 0; kt < 8; kt++) {
            float x0 = __shfl_sync(0xffffffffu, P[kt][0], sA);
            float x1 = __shfl_sync(0xffffffffu, P[kt][1], sA);
            float y0 = __shfl_sync(0xffffffffu, P[kt][0], sB);
            float y1 = __shfl_sync(0xffffffffu, P[kt][1], sB);
            float z0 = __shfl_sync(0xffffffffu, P[kt][2], sA);
            float z1 = __shfl_sync(0xffffffffu, P[kt][3], sA);
            float u0 = __shfl_sync(0xffffffffu, P[kt][2], sB);
            float u1 = __shfl_sync(0xffffffffu, P[kt][3], sB);
            uint32_t a[4];
            a[0] = __float_as_uint(hi ? x1 : x0);
            a[1] = __float_as_uint(hi ? z1 : z0);
            a[2] = __float_as_uint(hi ? y1 : y0);
            a[3] = __float_as_uint(hi ? u1 : u0);
#pragma unroll
            for (int n2 = 0; n2 < 3; n2++) {
                float2 bb = *(const float2*)&svT[(n2 * 8 + g) * 132 + mb + kt * 8 + 2 * th];
                uint32_t b[2] = {__float_as_uint(bb.x), __float_as_uint(bb.y)};
                mma_tf32(o[n2], a, b);
            }
        }
        float* ob = g_xout + ((size_t)wi * 240 + h * 20) * 128;
#pragma unroll
        for (int n2 = 0; n2 < 3; n2++) {
            int d0 = n2 * 8 + 2 * th, d1 = d0 + 1;
            if (d0 < 20) {
                ob[d0 * 128 + r0 + g]     = f2tf32(o[n2][0] * invA);
                ob[d0 * 128 + r0 + 8 + g] = f2tf32(o[n2][2] * invB);
            }
            if (d1 < 20) {
                ob[d1 * 128 + r0 + g]     = f2tf32(o[n2][1] * invA);
                ob[d1 * 128 + r0 + 8 + g] = f2tf32(o[n2][3] * invB);
            }
        }
    }
}

// ---------------- launch ----------------
extern "C" void kernel_launch(void* const* d_in, const int* in_sizes, int n_in,
                              void* d_out, int out_size) {
    const float* x          = (const float*)d_in[0];
    const float* g1         = (const float*)d_in[2];
    const float* b1         = (const float*)d_in[3];
    const float* qkv_self_w = (const float*)d_in[4];
    const float* qkv_self_b = (const float*)d_in[5];
    const float* qkv_mut_w  = (const float*)d_in[6];
    const float* qkv_mut_b  = (const float*)d_in[7];
    const float* proj_w     = (const float*)d_in[8];
    const float* proj_b     = (const float*)d_in[9];
    const float* rpb        = (const float*)d_in[10];
    const float* pos        = (const float*)d_in[11];
    const float* g2         = (const float*)d_in[12];
    const float* b2         = (const float*)d_in[13];
    const float* fc11_w     = (const float*)d_in[14];
    const float* fc11_b     = (const float*)d_in[15];
    const float* fc12_w     = (const float*)d_in[16];
    const float* fc12_b     = (const float*)d_in[17];
    const float* fc2_w      = (const float*)d_in[18];
    const float* fc2_b      = (const float*)d_in[19];
    float* out = (float*)d_out;

    float* xw   = nullptr; cudaGetSymbolAddress((void**)&xw,   g_xw);
    float* xwm  = nullptr; cudaGetSymbolAddress((void**)&xwm,  g_xwm);
    float* qkvs = nullptr; cudaGetSymbolAddress((void**)&qkvs, g_qkv_s);
    float* qkvm = nullptr; cudaGetSymbolAddress((void**)&qkvm, g_qkv_m);
    float* xo   = nullptr; cudaGetSymbolAddress((void**)&xo,   g_xout);
    float* xres = nullptr; cudaGetSymbolAddress((void**)&xres, g_xres);
    float* zb   = nullptr; cudaGetSymbolAddress((void**)&zb,   g_z);
    float* hb   = nullptr; cudaGetSymbolAddress((void**)&hb,   g_h);
    float* actb = nullptr; cudaGetSymbolAddress((void**)&actb, g_act);
    float* wts  = nullptr; cudaGetSymbolAddress((void**)&wts,  g_wts);

    // 0. round weights to tf32
    k_wcvt<<<(64800 + 255) / 256, 256>>>(qkv_self_w, qkv_mut_w, proj_w,
                                         fc11_w, fc12_w, fc2_w);
    // 1. LN1 + roll + window partition (+ pos-biased copy)
    k_ln1<<<NTOK / 8, 256>>>(x, g1, b1, pos);
    // 2. QKV self (-> [win][360][128])
    k_gemm<120, 0, 1, 0><<<dim3(NTOK / 128, 3), 256>>>(
        xw, wts + W_QS, nullptr, qkv_self_b, nullptr, nullptr, qkvs, 360);
    // 3. QKV mutual (-> [win][360][128])
    k_gemm<120, 0, 1, 0><<<dim3(NTOK / 128, 3), 256>>>(
        xwm, wts + W_QM, nullptr, qkv_mut_b, nullptr, nullptr, qkvm, 360);
    // 4. tensor-core attention (-> g_xout [win][240][128])
    k_attn<<<dim3(NWIN, 6), 256>>>(rpb);
    // 5. proj + window-reverse + roll-back + shortcut add
    k_gemm<240, 2, 0, 2><<<dim3(NTOK / 128, 1), 256>>>(
        xo, wts + W_PR, nullptr, proj_b, nullptr, x, xres, 120);
    // 6. LN2
    k_ln2<<<NTOK / 8, 256>>>(g2, b2);
    // 7. fc11 | fc12 (EPI 3 selects split B source)
    k_gemm<120, 0, 0, 3><<<dim3(NTOK / 128, 4), 256>>>(
        zb, wts + W_F11, wts + W_F12, fc11_b, fc12_b, nullptr, hb, 480);
    // 8. gated gelu elementwise
    k_act<<<(NTOK * 60 + 255) / 256, 256>>>();
    // 9. fc2 + residual -> out
    k_gemm<240, 0, 0, 4><<<dim3(NTOK / 128, 1), 256>>>(
        actb, wts + W_F2, nullptr, fc2_b, nullptr, xres, out, 120);
}